// round 16
// baseline (speedup 1.0000x reference)
#include <cuda_runtime.h>
#include <cuda_bf16.h>

// Problem constants (fixed by setup_inputs)
#define NN   8192      // nodes
#define INF  512       // in_features
#define HH   64        // hidden
#define DEG  32
#define EE   (NN * DEG)

#define FRONT_BLOCKS 128
#define ROWS_PER_FB  (NN / FRONT_BLOCKS)   // 64

// Scratch (__device__ globals; no allocation allowed)
__device__ float g_s1[NN];
__device__ float g_s2[NN];

// ---------------------------------------------------------------------------
// K1 "front": projection + scores. 128 blocks x 512 threads.
// Every block fires the PDL trigger at entry so k_row launches immediately.
// Phase A: thread t computes v1[t], v2[t] (16 independent float4 loads).
// Phase B: scores for 64 rows/block (4 rows per warp, float4 + shuffle).
// ---------------------------------------------------------------------------
__global__ void __launch_bounds__(512) k_front(const float* __restrict__ x,
                                               const float* __restrict__ W,
                                               const float* __restrict__ a)
{
    cudaTriggerProgrammaticLaunchCompletion();

    __shared__ float sa[2 * HH];
    __shared__ float sv1[INF];
    __shared__ float sv2[INF];

    const int t = threadIdx.x;
    const int warp = t >> 5, lane = t & 31;

    if (t < 2 * HH) sa[t] = a[t];
    __syncthreads();

    // ---- Phase A: v1, v2 — one W row per thread, 16 independent loads ---
    {
        const float4* wr = (const float4*)(W + (size_t)t * HH);
        float acc1 = 0.f, acc2 = 0.f;
#pragma unroll
        for (int i = 0; i < HH / 4; ++i) {
            float4 wv = wr[i];
            int b = 4 * i;
            acc1 = fmaf(wv.x, sa[b + 0], acc1);
            acc1 = fmaf(wv.y, sa[b + 1], acc1);
            acc1 = fmaf(wv.z, sa[b + 2], acc1);
            acc1 = fmaf(wv.w, sa[b + 3], acc1);
            acc2 = fmaf(wv.x, sa[HH + b + 0], acc2);
            acc2 = fmaf(wv.y, sa[HH + b + 1], acc2);
            acc2 = fmaf(wv.z, sa[HH + b + 2], acc2);
            acc2 = fmaf(wv.w, sa[HH + b + 3], acc2);
        }
        sv1[t] = acc1;
        sv2[t] = acc2;
    }
    __syncthreads();

    // ---- Phase B: scores for 64 rows (warp handles 4 consecutive rows) --
    int row0 = blockIdx.x * ROWS_PER_FB + warp * 4;
#pragma unroll
    for (int j = 0; j < 4; ++j) {
        int row = row0 + j;
        const float4* xr = (const float4*)(x + (size_t)row * INF);
        float a1 = 0.f, a2 = 0.f;
#pragma unroll
        for (int i = 0; i < 4; ++i) {
            int idx = lane + 32 * i;
            float4 v = xr[idx];
            int b = idx * 4;
            a1 = fmaf(v.x, sv1[b + 0], a1);
            a1 = fmaf(v.y, sv1[b + 1], a1);
            a1 = fmaf(v.z, sv1[b + 2], a1);
            a1 = fmaf(v.w, sv1[b + 3], a1);
            a2 = fmaf(v.x, sv2[b + 0], a2);
            a2 = fmaf(v.y, sv2[b + 1], a2);
            a2 = fmaf(v.z, sv2[b + 2], a2);
            a2 = fmaf(v.w, sv2[b + 3], a2);
        }
#pragma unroll
        for (int off = 16; off > 0; off >>= 1) {
            a1 += __shfl_down_sync(0xffffffffu, a1, off);
            a2 += __shfl_down_sync(0xffffffffu, a2, off);
        }
        if (lane == 0) { g_s1[row] = a1; g_s2[row] = a2; }
    }
}

// ---------------------------------------------------------------------------
// K2 "row": launched with PDL stream serialization; starts while k_front
// runs. One block per row s:
//   (0) warp 0 prefetches the row's dst indices (ei is an input, ready now),
//   (1) all warps stream unconditional float4 zeros over the 32KB row,
//   (2) __syncthreads(): orders every zero-store in this block BEFORE the
//       band write (the band columns live in slots zeroed by other warps —
//       without this barrier the band write can race the zero stores, which
//       is exactly the replay divergence seen in R15). Warps 1..7 retire at
//       the barrier; only warp 0 proceeds.
//   (3) warp 0: grid-dependency wait for k_front (HW, no polling), then
//       compute + write the 32 normalized band entries.
// exp > 0 => row sum > 0 always, so no zero-row diagonal case exists.
// ---------------------------------------------------------------------------
__global__ void __launch_bounds__(256) k_row(const int* __restrict__ ei,
                                             float* __restrict__ out)
{
    int s = blockIdx.x;
    int t = threadIdx.x;
    float* row = out + (size_t)s * NN;

    // (0) prefetch dst index before the fill (off the post-sync path)
    int d = 0;
    if (t < DEG)
        d = __ldg(&ei[EE + s * DEG + t]);

    // (1) streaming zero-fill — proven 6.8 TB/s pattern
    float4* r4 = (float4*)row;
    const float4 z = make_float4(0.f, 0.f, 0.f, 0.f);
#pragma unroll
    for (int i = 0; i < 8; ++i)
        __stcs(&r4[t + 256 * i], z);

    // (2) order zero stores before the band write; non-band warps retire here
    __syncthreads();

    // (3) only warp 0 waits for k_front, then writes the band
    if (t < DEG) {
        cudaGridDependencySynchronize();

        float v = g_s1[s] + g_s2[d];
        v = (v >= 0.f) ? v : 0.1f * v;      // leaky_relu slope 0.1
        float c = expf(v);
        float sum = c;
#pragma unroll
        for (int off = 16; off > 0; off >>= 1)
            sum += __shfl_xor_sync(0xffffffffu, sum, off);
        row[d] = c / sum;
    }
}

extern "C" void kernel_launch(void* const* d_in, const int* in_sizes, int n_in,
                              void* d_out, int out_size)
{
    const float* x  = (const float*)d_in[0];   // [N, IN]
    const float* W  = (const float*)d_in[1];   // [IN, H]
    const float* a  = (const float*)d_in[2];   // [2H, 1]
    const int*   ei = (const int*)  d_in[3];   // [2, E]
    float* out = (float*)d_out;                // [N, N]

    // Front kernel: normal launch on the capture stream.
    k_front<<<FRONT_BLOCKS, 512>>>(x, W, a);

    // Fill kernel: PDL — launches as soon as k_front's blocks trigger.
    cudaLaunchConfig_t cfg = {};
    cfg.gridDim  = dim3(NN, 1, 1);
    cfg.blockDim = dim3(256, 1, 1);
    cfg.dynamicSmemBytes = 0;
    cfg.stream = 0;
    cudaLaunchAttribute attr[1];
    attr[0].id = cudaLaunchAttributeProgrammaticStreamSerialization;
    attr[0].val.programmaticStreamSerializationAllowed = 1;
    cfg.attrs = attr;
    cfg.numAttrs = 1;
    cudaLaunchKernelEx(&cfg, k_row, ei, out);
}